// round 3
// baseline (speedup 1.0000x reference)
#include <cuda_runtime.h>

#define D 128
#define NMAX 50000
#define EMAX 600000

// allocation-free scratch
__device__ float g_agg[(size_t)NMAX * D];
__device__ int   g_deg[NMAX];
__device__ int   g_off[NMAX + 1];
__device__ int   g_cur[NMAX];
__device__ int   g_eid[EMAX];

// ---------------------------------------------------------------------------
// 1) histogram of destination degrees
// ---------------------------------------------------------------------------
__global__ void hist_kernel(const int* __restrict__ dst, int* __restrict__ deg, int E) {
    int e = blockIdx.x * blockDim.x + threadIdx.x;
    if (e < E) atomicAdd(&deg[__ldg(dst + e)], 1);
}

// ---------------------------------------------------------------------------
// 2) single-block exclusive prefix scan over N (+ total at off[N])
// ---------------------------------------------------------------------------
__global__ void __launch_bounds__(1024)
scan_kernel(const int* __restrict__ deg, int* __restrict__ off,
            int* __restrict__ cur, int N) {
    __shared__ int ssum[1024];
    const int tid = threadIdx.x;
    const int per = (N + 1023) / 1024;
    const int start = tid * per;
    const int end   = min(start + per, N);

    int s = 0;
    for (int i = start; i < end; i++) s += deg[i];
    ssum[tid] = s;
    __syncthreads();

    // Hillis-Steele inclusive scan
    for (int d = 1; d < 1024; d <<= 1) {
        int v = 0;
        if (tid >= d) v = ssum[tid - d];
        __syncthreads();
        if (tid >= d) ssum[tid] += v;
        __syncthreads();
    }

    int run = (tid > 0) ? ssum[tid - 1] : 0;
    for (int i = start; i < end; i++) {
        off[i] = run;
        cur[i] = run;
        run += deg[i];
    }
    if (tid == 1023) off[N] = ssum[1023];
}

// ---------------------------------------------------------------------------
// 3) fill CSR edge-id buckets
// ---------------------------------------------------------------------------
__global__ void fill_kernel(const int* __restrict__ dst, int* __restrict__ cur,
                            int* __restrict__ eid, int E) {
    int e = blockIdx.x * blockDim.x + threadIdx.x;
    if (e < E) {
        int pos = atomicAdd(&cur[__ldg(dst + e)], 1);
        eid[pos] = e;
    }
}

// ---------------------------------------------------------------------------
// 4) gather-reduce: warp per node. agg[n] = h[n] * sum_{e in bucket(n)} e_h[e]
// ---------------------------------------------------------------------------
__global__ void gather_kernel(const float* __restrict__ h,
                              const float* __restrict__ e_h,
                              const int* __restrict__ off,
                              const int* __restrict__ eid,
                              float* __restrict__ agg, int N) {
    int n    = blockIdx.x * (blockDim.x >> 5) + (threadIdx.x >> 5);
    int lane = threadIdx.x & 31;
    if (n >= N) return;

    int s = __ldg(off + n);
    int t = __ldg(off + n + 1);

    float4 acc0 = make_float4(0.f, 0.f, 0.f, 0.f);
    float4 acc1 = make_float4(0.f, 0.f, 0.f, 0.f);

    int i = s;
    for (; i + 1 < t; i += 2) {
        int e0 = __ldg(eid + i);
        int e1 = __ldg(eid + i + 1);
        float4 v0 = ((const float4*)(e_h + (size_t)e0 * D))[lane];
        float4 v1 = ((const float4*)(e_h + (size_t)e1 * D))[lane];
        acc0.x += v0.x; acc0.y += v0.y; acc0.z += v0.z; acc0.w += v0.w;
        acc1.x += v1.x; acc1.y += v1.y; acc1.z += v1.z; acc1.w += v1.w;
    }
    if (i < t) {
        int e0 = __ldg(eid + i);
        float4 v0 = ((const float4*)(e_h + (size_t)e0 * D))[lane];
        acc0.x += v0.x; acc0.y += v0.y; acc0.z += v0.z; acc0.w += v0.w;
    }

    float4 hv = ((const float4*)(h + (size_t)n * D))[lane];
    float4 r;
    r.x = (acc0.x + acc1.x) * hv.x;
    r.y = (acc0.y + acc1.y) * hv.y;
    r.z = (acc0.z + acc1.z) * hv.z;
    r.w = (acc0.w + acc1.w) * hv.w;
    ((float4*)(agg + (size_t)n * D))[lane] = r;
}

// ---------------------------------------------------------------------------
// 5) GEMM: out[n][j] = (sum_k agg[n][k] * W[j][k] + b[j]) * norm[n]
//    (unchanged from R2 — at FP32 FFMA roofline)
// ---------------------------------------------------------------------------
#define KC 32
#define APAD 132

__global__ void __launch_bounds__(256)
gemm_kernel(const float* __restrict__ agg,
            const float* __restrict__ W,
            const float* __restrict__ b,
            const float* __restrict__ norm,
            float* __restrict__ out,
            int N) {
    __shared__ float As[KC][APAD];   // [k][row]
    __shared__ float Ws[KC][APAD];   // [k][col]

    const int tid = threadIdx.x;
    const int tx = tid & 15;
    const int ty = tid >> 4;
    const int rowBase = blockIdx.x * 128;

    float acc[8][8];
    #pragma unroll
    for (int i = 0; i < 8; i++)
        #pragma unroll
        for (int j = 0; j < 8; j++) acc[i][j] = 0.0f;

    for (int kk = 0; kk < D; kk += KC) {
        #pragma unroll
        for (int t = 0; t < 4; t++) {
            int i  = tid + t * 256;
            int r  = i >> 3;
            int c4 = i & 7;
            int grow = rowBase + r;
            float4 v = make_float4(0.f, 0.f, 0.f, 0.f);
            if (grow < N)
                v = ((const float4*)(agg + (size_t)grow * D + kk))[c4];
            As[c4 * 4 + 0][r] = v.x;
            As[c4 * 4 + 1][r] = v.y;
            As[c4 * 4 + 2][r] = v.z;
            As[c4 * 4 + 3][r] = v.w;
        }
        #pragma unroll
        for (int t = 0; t < 4; t++) {
            int i  = tid + t * 256;
            int j  = i >> 3;
            int c4 = i & 7;
            float4 v = ((const float4*)(W + (size_t)j * D + kk))[c4];
            Ws[c4 * 4 + 0][j] = v.x;
            Ws[c4 * 4 + 1][j] = v.y;
            Ws[c4 * 4 + 2][j] = v.z;
            Ws[c4 * 4 + 3][j] = v.w;
        }
        __syncthreads();

        #pragma unroll
        for (int k = 0; k < KC; k++) {
            float4 a0 = *(const float4*)&As[k][ty * 4];
            float4 a1 = *(const float4*)&As[k][ty * 4 + 64];
            float4 w0 = *(const float4*)&Ws[k][tx * 4];
            float4 w1 = *(const float4*)&Ws[k][tx * 4 + 64];
            float a[8] = {a0.x, a0.y, a0.z, a0.w, a1.x, a1.y, a1.z, a1.w};
            float w[8] = {w0.x, w0.y, w0.z, w0.w, w1.x, w1.y, w1.z, w1.w};
            #pragma unroll
            for (int i = 0; i < 8; i++)
                #pragma unroll
                for (int j = 0; j < 8; j++)
                    acc[i][j] = fmaf(a[i], w[j], acc[i][j]);
        }
        __syncthreads();
    }

    #pragma unroll
    for (int iq = 0; iq < 2; iq++) {
        #pragma unroll
        for (int i = 0; i < 4; i++) {
            int n = rowBase + ty * 4 + iq * 64 + i;
            if (n >= N) continue;
            float nm = __ldg(norm + n);
            #pragma unroll
            for (int jq = 0; jq < 2; jq++) {
                int col = tx * 4 + jq * 64;
                float4 bb = *(const float4*)(b + col);
                float4 r;
                r.x = (acc[iq * 4 + i][jq * 4 + 0] + bb.x) * nm;
                r.y = (acc[iq * 4 + i][jq * 4 + 1] + bb.y) * nm;
                r.z = (acc[iq * 4 + i][jq * 4 + 2] + bb.z) * nm;
                r.w = (acc[iq * 4 + i][jq * 4 + 3] + bb.w) * nm;
                *(float4*)(out + (size_t)n * D + col) = r;
            }
        }
    }
}

extern "C" void kernel_launch(void* const* d_in, const int* in_sizes, int n_in,
                              void* d_out, int out_size) {
    const float* h    = (const float*)d_in[0];
    const float* e_h  = (const float*)d_in[1];
    const float* norm = (const float*)d_in[2];
    const int*   dst  = (const int*)d_in[3];
    const float* W    = (const float*)d_in[4];
    const float* b    = (const float*)d_in[5];
    float*       out  = (float*)d_out;

    const int N = in_sizes[2];
    const int E = in_sizes[3];

    float* agg; int* deg; int* off; int* cur; int* eid;
    cudaGetSymbolAddress((void**)&agg, g_agg);
    cudaGetSymbolAddress((void**)&deg, g_deg);
    cudaGetSymbolAddress((void**)&off, g_off);
    cudaGetSymbolAddress((void**)&cur, g_cur);
    cudaGetSymbolAddress((void**)&eid, g_eid);

    cudaMemsetAsync(deg, 0, (size_t)N * sizeof(int), 0);

    hist_kernel<<<(E + 255) / 256, 256>>>(dst, deg, E);
    scan_kernel<<<1, 1024>>>(deg, off, cur, N);
    fill_kernel<<<(E + 255) / 256, 256>>>(dst, cur, eid, E);

    {   // warp per node
        int threads = 256;
        int wpb = threads / 32;
        gather_kernel<<<(N + wpb - 1) / wpb, threads>>>(h, e_h, off, eid, agg, N);
    }

    gemm_kernel<<<(N + 127) / 128, 256>>>(agg, W, b, norm, out, N);
}

// round 4
// speedup vs baseline: 1.4770x; 1.4770x over previous
#include <cuda_runtime.h>

#define D 128
#define NMAX 50000
#define EMAX 600000
#define SCAN_B 1024
#define NBMAX 64   // ceil(50000/1024) = 49

// allocation-free scratch
__device__ float g_agg[(size_t)NMAX * D];
__device__ int   g_deg[NMAX];
__device__ int   g_off[NMAX + 1];
__device__ int   g_cur[NMAX];
__device__ int   g_eid[EMAX];
__device__ int   g_part[NBMAX];

// ---------------------------------------------------------------------------
// 1) histogram of destination degrees
// ---------------------------------------------------------------------------
__global__ void hist_kernel(const int* __restrict__ dst, int* __restrict__ deg, int E) {
    int e = blockIdx.x * blockDim.x + threadIdx.x;
    if (e < E) atomicAdd(&deg[__ldg(dst + e)], 1);
}

// ---------------------------------------------------------------------------
// 2a) per-block sums of deg (coalesced)
// ---------------------------------------------------------------------------
__global__ void __launch_bounds__(SCAN_B)
blocksum_kernel(const int* __restrict__ deg, int* __restrict__ part, int N) {
    __shared__ int red[32];
    int i = blockIdx.x * SCAN_B + threadIdx.x;
    int v = (i < N) ? deg[i] : 0;
    #pragma unroll
    for (int o = 16; o > 0; o >>= 1) v += __shfl_down_sync(0xffffffffu, v, o);
    if ((threadIdx.x & 31) == 0) red[threadIdx.x >> 5] = v;
    __syncthreads();
    if (threadIdx.x < 32) {
        int s = red[threadIdx.x];
        #pragma unroll
        for (int o = 16; o > 0; o >>= 1) s += __shfl_down_sync(0xffffffffu, s, o);
        if (threadIdx.x == 0) part[blockIdx.x] = s;
    }
}

// ---------------------------------------------------------------------------
// 2b) exclusive scan of <=64 block partials (1 block, 64 threads)
// ---------------------------------------------------------------------------
__global__ void scanpart_kernel(int* __restrict__ part, int nb) {
    int t = threadIdx.x;
    int v = (t < nb) ? part[t] : 0;
    int lane = t & 31, w = t >> 5;
    int inc = v;
    #pragma unroll
    for (int o = 1; o < 32; o <<= 1) {
        int u = __shfl_up_sync(0xffffffffu, inc, o);
        if (lane >= o) inc += u;
    }
    __shared__ int ws[2];
    if (lane == 31) ws[w] = inc;
    __syncthreads();
    if (w == 1) inc += ws[0];
    if (t < nb) part[t] = inc - v;   // exclusive
}

// ---------------------------------------------------------------------------
// 2c) final scan: off[i] = part[blk] + exclusive-in-block; cur = off
// ---------------------------------------------------------------------------
__global__ void __launch_bounds__(SCAN_B)
scatter_kernel(const int* __restrict__ deg, const int* __restrict__ part,
               int* __restrict__ off, int* __restrict__ cur, int N) {
    __shared__ int wsum[32];
    int i = blockIdx.x * SCAN_B + threadIdx.x;
    int v = (i < N) ? deg[i] : 0;
    int lane = threadIdx.x & 31, w = threadIdx.x >> 5;

    int inc = v;
    #pragma unroll
    for (int o = 1; o < 32; o <<= 1) {
        int u = __shfl_up_sync(0xffffffffu, inc, o);
        if (lane >= o) inc += u;
    }
    if (lane == 31) wsum[w] = inc;
    __syncthreads();
    if (w == 0) {
        int s = wsum[lane];
        int si = s;
        #pragma unroll
        for (int o = 1; o < 32; o <<= 1) {
            int u = __shfl_up_sync(0xffffffffu, si, o);
            if (lane >= o) si += u;
        }
        wsum[lane] = si - s;   // exclusive warp bases
    }
    __syncthreads();

    int excl = part[blockIdx.x] + wsum[w] + (inc - v);
    if (i < N) {
        off[i] = excl;
        cur[i] = excl;
        if (i == N - 1) off[N] = excl + v;
    }
}

// ---------------------------------------------------------------------------
// 3) fill CSR edge-id buckets
// ---------------------------------------------------------------------------
__global__ void fill_kernel(const int* __restrict__ dst, int* __restrict__ cur,
                            int* __restrict__ eid, int E) {
    int e = blockIdx.x * blockDim.x + threadIdx.x;
    if (e < E) {
        int pos = atomicAdd(&cur[__ldg(dst + e)], 1);
        eid[pos] = e;
    }
}

// ---------------------------------------------------------------------------
// 4) gather-reduce: warp per node. agg[n] = h[n] * sum_{e in bucket(n)} e_h[e]
// ---------------------------------------------------------------------------
__global__ void gather_kernel(const float* __restrict__ h,
                              const float* __restrict__ e_h,
                              const int* __restrict__ off,
                              const int* __restrict__ eid,
                              float* __restrict__ agg, int N) {
    int n    = blockIdx.x * (blockDim.x >> 5) + (threadIdx.x >> 5);
    int lane = threadIdx.x & 31;
    if (n >= N) return;

    int s = __ldg(off + n);
    int t = __ldg(off + n + 1);

    float4 acc0 = make_float4(0.f, 0.f, 0.f, 0.f);
    float4 acc1 = make_float4(0.f, 0.f, 0.f, 0.f);

    int i = s;
    for (; i + 1 < t; i += 2) {
        int e0 = __ldg(eid + i);
        int e1 = __ldg(eid + i + 1);
        float4 v0 = ((const float4*)(e_h + (size_t)e0 * D))[lane];
        float4 v1 = ((const float4*)(e_h + (size_t)e1 * D))[lane];
        acc0.x += v0.x; acc0.y += v0.y; acc0.z += v0.z; acc0.w += v0.w;
        acc1.x += v1.x; acc1.y += v1.y; acc1.z += v1.z; acc1.w += v1.w;
    }
    if (i < t) {
        int e0 = __ldg(eid + i);
        float4 v0 = ((const float4*)(e_h + (size_t)e0 * D))[lane];
        acc0.x += v0.x; acc0.y += v0.y; acc0.z += v0.z; acc0.w += v0.w;
    }

    float4 hv = ((const float4*)(h + (size_t)n * D))[lane];
    float4 r;
    r.x = (acc0.x + acc1.x) * hv.x;
    r.y = (acc0.y + acc1.y) * hv.y;
    r.z = (acc0.z + acc1.z) * hv.z;
    r.w = (acc0.w + acc1.w) * hv.w;
    ((float4*)(agg + (size_t)n * D))[lane] = r;
}

// ---------------------------------------------------------------------------
// 5) GEMM: out[n][j] = (sum_k agg[n][k] * W[j][k] + b[j]) * norm[n]
// ---------------------------------------------------------------------------
#define KC 32
#define APAD 132

__global__ void __launch_bounds__(256)
gemm_kernel(const float* __restrict__ agg,
            const float* __restrict__ W,
            const float* __restrict__ b,
            const float* __restrict__ norm,
            float* __restrict__ out,
            int N) {
    __shared__ float As[KC][APAD];
    __shared__ float Ws[KC][APAD];

    const int tid = threadIdx.x;
    const int tx = tid & 15;
    const int ty = tid >> 4;
    const int rowBase = blockIdx.x * 128;

    float acc[8][8];
    #pragma unroll
    for (int i = 0; i < 8; i++)
        #pragma unroll
        for (int j = 0; j < 8; j++) acc[i][j] = 0.0f;

    for (int kk = 0; kk < D; kk += KC) {
        #pragma unroll
        for (int t = 0; t < 4; t++) {
            int i  = tid + t * 256;
            int r  = i >> 3;
            int c4 = i & 7;
            int grow = rowBase + r;
            float4 v = make_float4(0.f, 0.f, 0.f, 0.f);
            if (grow < N)
                v = ((const float4*)(agg + (size_t)grow * D + kk))[c4];
            As[c4 * 4 + 0][r] = v.x;
            As[c4 * 4 + 1][r] = v.y;
            As[c4 * 4 + 2][r] = v.z;
            As[c4 * 4 + 3][r] = v.w;
        }
        #pragma unroll
        for (int t = 0; t < 4; t++) {
            int i  = tid + t * 256;
            int j  = i >> 3;
            int c4 = i & 7;
            float4 v = ((const float4*)(W + (size_t)j * D + kk))[c4];
            Ws[c4 * 4 + 0][j] = v.x;
            Ws[c4 * 4 + 1][j] = v.y;
            Ws[c4 * 4 + 2][j] = v.z;
            Ws[c4 * 4 + 3][j] = v.w;
        }
        __syncthreads();

        #pragma unroll
        for (int k = 0; k < KC; k++) {
            float4 a0 = *(const float4*)&As[k][ty * 4];
            float4 a1 = *(const float4*)&As[k][ty * 4 + 64];
            float4 w0 = *(const float4*)&Ws[k][tx * 4];
            float4 w1 = *(const float4*)&Ws[k][tx * 4 + 64];
            float a[8] = {a0.x, a0.y, a0.z, a0.w, a1.x, a1.y, a1.z, a1.w};
            float w[8] = {w0.x, w0.y, w0.z, w0.w, w1.x, w1.y, w1.z, w1.w};
            #pragma unroll
            for (int i = 0; i < 8; i++)
                #pragma unroll
                for (int j = 0; j < 8; j++)
                    acc[i][j] = fmaf(a[i], w[j], acc[i][j]);
        }
        __syncthreads();
    }

    #pragma unroll
    for (int iq = 0; iq < 2; iq++) {
        #pragma unroll
        for (int i = 0; i < 4; i++) {
            int n = rowBase + ty * 4 + iq * 64 + i;
            if (n >= N) continue;
            float nm = __ldg(norm + n);
            #pragma unroll
            for (int jq = 0; jq < 2; jq++) {
                int col = tx * 4 + jq * 64;
                float4 bb = *(const float4*)(b + col);
                float4 r;
                r.x = (acc[iq * 4 + i][jq * 4 + 0] + bb.x) * nm;
                r.y = (acc[iq * 4 + i][jq * 4 + 1] + bb.y) * nm;
                r.z = (acc[iq * 4 + i][jq * 4 + 2] + bb.z) * nm;
                r.w = (acc[iq * 4 + i][jq * 4 + 3] + bb.w) * nm;
                *(float4*)(out + (size_t)n * D + col) = r;
            }
        }
    }
}

extern "C" void kernel_launch(void* const* d_in, const int* in_sizes, int n_in,
                              void* d_out, int out_size) {
    const float* h    = (const float*)d_in[0];
    const float* e_h  = (const float*)d_in[1];
    const float* norm = (const float*)d_in[2];
    const int*   dst  = (const int*)d_in[3];
    const float* W    = (const float*)d_in[4];
    const float* b    = (const float*)d_in[5];
    float*       out  = (float*)d_out;

    const int N = in_sizes[2];
    const int E = in_sizes[3];

    float* agg; int* deg; int* off; int* cur; int* eid; int* part;
    cudaGetSymbolAddress((void**)&agg, g_agg);
    cudaGetSymbolAddress((void**)&deg, g_deg);
    cudaGetSymbolAddress((void**)&off, g_off);
    cudaGetSymbolAddress((void**)&cur, g_cur);
    cudaGetSymbolAddress((void**)&eid, g_eid);
    cudaGetSymbolAddress((void**)&part, g_part);

    cudaMemsetAsync(deg, 0, (size_t)N * sizeof(int), 0);

    hist_kernel<<<(E + 255) / 256, 256>>>(dst, deg, E);

    int nb = (N + SCAN_B - 1) / SCAN_B;
    blocksum_kernel<<<nb, SCAN_B>>>(deg, part, N);
    scanpart_kernel<<<1, 64>>>(part, nb);
    scatter_kernel<<<nb, SCAN_B>>>(deg, part, off, cur, N);

    fill_kernel<<<(E + 255) / 256, 256>>>(dst, cur, eid, E);

    {
        int threads = 256;
        int wpb = threads / 32;
        gather_kernel<<<(N + wpb - 1) / wpb, threads>>>(h, e_h, off, eid, agg, N);
    }

    gemm_kernel<<<(N + 127) / 128, 256>>>(agg, W, b, norm, out, N);
}

// round 6
// speedup vs baseline: 1.6858x; 1.1414x over previous
#include <cuda_runtime.h>
#include <cstdint>

#define D 128
#define NMAX 50000
#define EMAX 600000
#define SCAN_B 1024
#define NBMAX 64

// allocation-free scratch
__device__ float g_agg[(size_t)NMAX * D];
__device__ int   g_deg[NMAX];
__device__ int   g_off[NMAX + 1];
__device__ int   g_cur[NMAX];
__device__ int   g_eid[EMAX];
__device__ int   g_part[NBMAX];

// ============================ CSR build =====================================
__global__ void hist_kernel(const int* __restrict__ dst, int* __restrict__ deg, int E) {
    int e = blockIdx.x * blockDim.x + threadIdx.x;
    if (e < E) atomicAdd(&deg[__ldg(dst + e)], 1);
}

__global__ void __launch_bounds__(SCAN_B)
blocksum_kernel(const int* __restrict__ deg, int* __restrict__ part, int N) {
    __shared__ int red[32];
    int i = blockIdx.x * SCAN_B + threadIdx.x;
    int v = (i < N) ? deg[i] : 0;
    #pragma unroll
    for (int o = 16; o > 0; o >>= 1) v += __shfl_down_sync(0xffffffffu, v, o);
    if ((threadIdx.x & 31) == 0) red[threadIdx.x >> 5] = v;
    __syncthreads();
    if (threadIdx.x < 32) {
        int s = red[threadIdx.x];
        #pragma unroll
        for (int o = 16; o > 0; o >>= 1) s += __shfl_down_sync(0xffffffffu, s, o);
        if (threadIdx.x == 0) part[blockIdx.x] = s;
    }
}

__global__ void scanpart_kernel(int* __restrict__ part, int nb) {
    int t = threadIdx.x;
    int v = (t < nb) ? part[t] : 0;
    int lane = t & 31, w = t >> 5;
    int inc = v;
    #pragma unroll
    for (int o = 1; o < 32; o <<= 1) {
        int u = __shfl_up_sync(0xffffffffu, inc, o);
        if (lane >= o) inc += u;
    }
    __shared__ int ws[2];
    if (lane == 31) ws[w] = inc;
    __syncthreads();
    if (w == 1) inc += ws[0];
    if (t < nb) part[t] = inc - v;
}

__global__ void __launch_bounds__(SCAN_B)
scatter_kernel(const int* __restrict__ deg, const int* __restrict__ part,
               int* __restrict__ off, int* __restrict__ cur, int N) {
    __shared__ int wsum[32];
    int i = blockIdx.x * SCAN_B + threadIdx.x;
    int v = (i < N) ? deg[i] : 0;
    int lane = threadIdx.x & 31, w = threadIdx.x >> 5;
    int inc = v;
    #pragma unroll
    for (int o = 1; o < 32; o <<= 1) {
        int u = __shfl_up_sync(0xffffffffu, inc, o);
        if (lane >= o) inc += u;
    }
    if (lane == 31) wsum[w] = inc;
    __syncthreads();
    if (w == 0) {
        int s = wsum[lane];
        int si = s;
        #pragma unroll
        for (int o = 1; o < 32; o <<= 1) {
            int u = __shfl_up_sync(0xffffffffu, si, o);
            if (lane >= o) si += u;
        }
        wsum[lane] = si - s;
    }
    __syncthreads();
    int excl = part[blockIdx.x] + wsum[w] + (inc - v);
    if (i < N) {
        off[i] = excl;
        cur[i] = excl;
        if (i == N - 1) off[N] = excl + v;
    }
}

__global__ void fill_kernel(const int* __restrict__ dst, int* __restrict__ cur,
                            int* __restrict__ eid, int E) {
    int e = blockIdx.x * blockDim.x + threadIdx.x;
    if (e < E) {
        int pos = atomicAdd(&cur[__ldg(dst + e)], 1);
        eid[pos] = e;
    }
}

// ============================ gather ========================================
__global__ void gather_kernel(const float* __restrict__ h,
                              const float* __restrict__ e_h,
                              const int* __restrict__ off,
                              const int* __restrict__ eid,
                              float* __restrict__ agg, int N) {
    int n    = blockIdx.x * (blockDim.x >> 5) + (threadIdx.x >> 5);
    int lane = threadIdx.x & 31;
    if (n >= N) return;

    int s = __ldg(off + n);
    int t = __ldg(off + n + 1);

    float4 a0 = make_float4(0.f, 0.f, 0.f, 0.f);
    float4 a1 = make_float4(0.f, 0.f, 0.f, 0.f);
    float4 a2 = make_float4(0.f, 0.f, 0.f, 0.f);
    float4 a3 = make_float4(0.f, 0.f, 0.f, 0.f);

    int i = s;
    for (; i + 3 < t; i += 4) {
        int e0 = __ldg(eid + i);
        int e1 = __ldg(eid + i + 1);
        int e2 = __ldg(eid + i + 2);
        int e3 = __ldg(eid + i + 3);
        float4 v0 = ((const float4*)(e_h + (size_t)e0 * D))[lane];
        float4 v1 = ((const float4*)(e_h + (size_t)e1 * D))[lane];
        float4 v2 = ((const float4*)(e_h + (size_t)e2 * D))[lane];
        float4 v3 = ((const float4*)(e_h + (size_t)e3 * D))[lane];
        a0.x += v0.x; a0.y += v0.y; a0.z += v0.z; a0.w += v0.w;
        a1.x += v1.x; a1.y += v1.y; a1.z += v1.z; a1.w += v1.w;
        a2.x += v2.x; a2.y += v2.y; a2.z += v2.z; a2.w += v2.w;
        a3.x += v3.x; a3.y += v3.y; a3.z += v3.z; a3.w += v3.w;
    }
    for (; i < t; i++) {
        int e0 = __ldg(eid + i);
        float4 v0 = ((const float4*)(e_h + (size_t)e0 * D))[lane];
        a0.x += v0.x; a0.y += v0.y; a0.z += v0.z; a0.w += v0.w;
    }

    float4 hv = ((const float4*)(h + (size_t)n * D))[lane];
    float4 r;
    r.x = (a0.x + a1.x + a2.x + a3.x) * hv.x;
    r.y = (a0.y + a1.y + a2.y + a3.y) * hv.y;
    r.z = (a0.z + a1.z + a2.z + a3.z) * hv.z;
    r.w = (a0.w + a1.w + a2.w + a3.w) * hv.w;
    ((float4*)(agg + (size_t)n * D))[lane] = r;
}

// ============================ TF32 mma.sync GEMM ============================
// out[n][j] = (sum_k agg[n][k] * W[j][k] + b[j]) * norm[n]
// Block tile 128x128xK128; 8 warps in 4(M)x2(N); warp tile 32x64.
// Operands staged in smem as TF32-rounded fp32, row-major pad 132.
#define LDP 132
#define SM_BYTES (2 * 128 * LDP * 4)

__device__ __forceinline__ uint32_t f2tf32(float x) {
    uint32_t r;
    asm("cvt.rna.tf32.f32 %0, %1;" : "=r"(r) : "f"(x));
    return r;
}

__device__ __forceinline__ void mma_tf32(float* c, const uint32_t* a, const uint32_t* bb) {
    asm volatile(
        "mma.sync.aligned.m16n8k8.row.col.f32.tf32.tf32.f32 "
        "{%0,%1,%2,%3}, {%4,%5,%6,%7}, {%8,%9}, {%0,%1,%2,%3};"
        : "+f"(c[0]), "+f"(c[1]), "+f"(c[2]), "+f"(c[3])
        : "r"(a[0]), "r"(a[1]), "r"(a[2]), "r"(a[3]), "r"(bb[0]), "r"(bb[1]));
}

__global__ void __launch_bounds__(256, 1)
gemm_mma_kernel(const float* __restrict__ agg,
                const float* __restrict__ W,
                const float* __restrict__ b,
                const float* __restrict__ norm,
                float* __restrict__ out,
                int N) {
    extern __shared__ uint32_t sm[];
    uint32_t* As = sm;                 // [128][LDP] tf32 bits of agg rows
    uint32_t* Ws = sm + 128 * LDP;     // [128][LDP] tf32 bits of W rows

    const int tid = threadIdx.x;
    const int wid = tid >> 5;
    const int lane = tid & 31;
    const int rowBase = blockIdx.x * 128;

    // --- stage A (agg) and B (W) with tf32 rounding; one row per warp pass ---
    #pragma unroll
    for (int t = 0; t < 16; t++) {
        int idx = tid + t * 256;       // 0..4095
        int row = idx >> 5;            // 0..127
        int c4  = idx & 31;            // float4 index
        int grow = rowBase + row;
        float4 v = make_float4(0.f, 0.f, 0.f, 0.f);
        if (grow < N)
            v = ((const float4*)(agg + (size_t)grow * D))[c4];
        uint32_t* p = As + row * LDP + c4 * 4;
        p[0] = f2tf32(v.x); p[1] = f2tf32(v.y);
        p[2] = f2tf32(v.z); p[3] = f2tf32(v.w);
    }
    #pragma unroll
    for (int t = 0; t < 16; t++) {
        int idx = tid + t * 256;
        int row = idx >> 5;
        int c4  = idx & 31;
        float4 v = ((const float4*)(W + (size_t)row * D))[c4];
        uint32_t* p = Ws + row * LDP + c4 * 4;
        p[0] = f2tf32(v.x); p[1] = f2tf32(v.y);
        p[2] = f2tf32(v.z); p[3] = f2tf32(v.w);
    }
    __syncthreads();

    // warp tiling: wid&3 -> M group (32 rows), wid>>2 -> N group (64 cols)
    const int mBase = (wid & 3) * 32;
    const int nBase = (wid >> 2) * 64;
    const int gID = lane >> 2;   // 0..7
    const int tig = lane & 3;    // 0..3

    float acc[16][4];   // [mt*8+nt][4]
    #pragma unroll
    for (int i = 0; i < 16; i++)
        #pragma unroll
        for (int j = 0; j < 4; j++) acc[i][j] = 0.0f;

    #pragma unroll
    for (int ks = 0; ks < 16; ks++) {
        const int k0 = ks * 8;
        uint32_t a[2][4];
        #pragma unroll
        for (int mt = 0; mt < 2; mt++) {
            int r0 = mBase + mt * 16 + gID;
            a[mt][0] = As[(size_t)r0 * LDP + k0 + tig];
            a[mt][1] = As[(size_t)(r0 + 8) * LDP + k0 + tig];
            a[mt][2] = As[(size_t)r0 * LDP + k0 + tig + 4];
            a[mt][3] = As[(size_t)(r0 + 8) * LDP + k0 + tig + 4];
        }
        uint32_t bf[8][2];
        #pragma unroll
        for (int nt = 0; nt < 8; nt++) {
            int n = nBase + nt * 8 + gID;
            bf[nt][0] = Ws[(size_t)n * LDP + k0 + tig];
            bf[nt][1] = Ws[(size_t)n * LDP + k0 + tig + 4];
        }
        #pragma unroll
        for (int mt = 0; mt < 2; mt++)
            #pragma unroll
            for (int nt = 0; nt < 8; nt++)
                mma_tf32(acc[mt * 8 + nt], a[mt], bf[nt]);
    }

    // --- epilogue: (acc + b) * norm ---
    // c0,c1 -> row gID,   cols 2*tig, 2*tig+1
    // c2,c3 -> row gID+8, same cols
    #pragma unroll
    for (int mt = 0; mt < 2; mt++) {
        #pragma unroll
        for (int half = 0; half < 2; half++) {
            int m = rowBase + mBase + mt * 16 + half * 8 + gID;
            if (m >= N) continue;
            float nm = __ldg(norm + m);
            #pragma unroll
            for (int nt = 0; nt < 8; nt++) {
                int col = nBase + nt * 8 + tig * 2;
                float2 bb = *(const float2*)(b + col);
                float2 r;
                r.x = (acc[mt * 8 + nt][half * 2 + 0] + bb.x) * nm;
                r.y = (acc[mt * 8 + nt][half * 2 + 1] + bb.y) * nm;
                *(float2*)(out + (size_t)m * D + col) = r;
            }
        }
    }
}

// ============================ launch ========================================
extern "C" void kernel_launch(void* const* d_in, const int* in_sizes, int n_in,
                              void* d_out, int out_size) {
    const float* h    = (const float*)d_in[0];
    const float* e_h  = (const float*)d_in[1];
    const float* norm = (const float*)d_in[2];
    const int*   dst  = (const int*)d_in[3];
    const float* W    = (const float*)d_in[4];
    const float* b    = (const float*)d_in[5];
    float*       out  = (float*)d_out;

    const int N = in_sizes[2];
    const int E = in_sizes[3];

    float* agg; int* deg; int* off; int* cur; int* eid; int* part;
    cudaGetSymbolAddress((void**)&agg, g_agg);
    cudaGetSymbolAddress((void**)&deg, g_deg);
    cudaGetSymbolAddress((void**)&off, g_off);
    cudaGetSymbolAddress((void**)&cur, g_cur);
    cudaGetSymbolAddress((void**)&eid, g_eid);
    cudaGetSymbolAddress((void**)&part, g_part);

    cudaMemsetAsync(deg, 0, (size_t)N * sizeof(int), 0);

    hist_kernel<<<(E + 255) / 256, 256>>>(dst, deg, E);

    int nb = (N + SCAN_B - 1) / SCAN_B;
    blocksum_kernel<<<nb, SCAN_B>>>(deg, part, N);
    scanpart_kernel<<<1, 64>>>(part, nb);
    scatter_kernel<<<nb, SCAN_B>>>(deg, part, off, cur, N);

    fill_kernel<<<(E + 255) / 256, 256>>>(dst, cur, eid, E);

    {
        int threads = 256;
        int wpb = threads / 32;
        gather_kernel<<<(N + wpb - 1) / wpb, threads>>>(h, e_h, off, eid, agg, N);
    }

    cudaFuncSetAttribute(gemm_mma_kernel,
                         cudaFuncAttributeMaxDynamicSharedMemorySize, SM_BYTES);
    gemm_mma_kernel<<<(N + 127) / 128, 256, SM_BYTES>>>(agg, W, b, norm, out, N);
}